// round 14
// baseline (speedup 1.0000x reference)
#include <cuda_runtime.h>

#define NB 4
#define PRE 512
#define NC 2048
#define TANCH 261120
#define NBIN 4096
#define SHIFT 20
#define CANDCAP 2048
#define NBLK 264
#define SMAX 160
#define NINF __int_as_float(0xff800000)

// ---------------- scratch (device globals; zero-initialized) --------------
__device__ int g_ccnt[16];
__device__ int g_imgarr[NB];
__device__ unsigned long long g_rowany[NB][32];
__device__ unsigned long long g_cand[16][CANDCAP];
__device__ float g_box[NB][NC][5];                // pos-indexed
__device__ float g_score[NB][NC];                 // pos-indexed
__device__ unsigned char g_valid[NB][NC];         // pos-indexed
__device__ float g_geom[NB][NC][16];              // pos-indexed
__device__ unsigned long long g_key[NB][NC];
__device__ int g_perm[NB][NC];                    // sorted rank -> pos
__device__ unsigned char g_svalid[NB][NC];        // sorted order
__device__ float g_sscore[NB][NC];                // sorted order
__device__ unsigned long long g_mask[NB][NC][32];

__device__ const int c_aoff[4] = {0, 196608, 245760, 258048};
// static collect thresholds: ~top-900 quantile of N(0,1) per level size
// (exactness independent of these: out-of-range counts trigger exact fallback)
__device__ const float c_thr[4] = {2.605f, 2.090f, 1.4523f, 0.5446f};

__device__ __forceinline__ unsigned fflip(float f) {
    unsigned u = __float_as_uint(f);
    return (u & 0x80000000u) ? ~u : (u | 0x80000000u);
}
__device__ __forceinline__ float funflip(unsigned u) {
    return __uint_as_float((u & 0x80000000u) ? (u ^ 0x80000000u) : ~u);
}

__device__ __forceinline__ void map_block(int bx, int& b, int& lvl, int& c0, int& n) {
    b = bx / 66;
    int t = bx % 66;
    if (t < 48)      { lvl = 0; c0 = t * 4096;        n = 4096; }
    else if (t < 60) { lvl = 1; c0 = (t - 48) * 4096; n = 4096; }
    else if (t < 64) { lvl = 2; c0 = (t - 60) * 3072; n = 3072; }
    else             { lvl = 3; c0 = (t - 64) * 1536; n = 1536; }
}

// select the r-th (0-based) set bit of a 64-bit word
__device__ __forceinline__ int sel64(unsigned long long word, int r) {
    unsigned lo = (unsigned)word;
    int cl = __popc(lo);
    if (r < cl) return __fns(lo, 0, r + 1);
    return 32 + __fns((unsigned)(word >> 32), 0, r - cl + 1);
}

// ------------- stage 1: single-pass threshold collect ----------------------
__global__ __launch_bounds__(512) void select_kernel(const float* __restrict__ o0,
                                                     const float* __restrict__ o1,
                                                     const float* __restrict__ o2,
                                                     const float* __restrict__ o3) {
    int tid = threadIdx.x;
    int b, lvl, c0, n;
    map_block(blockIdx.x, b, lvl, c0, n);
    const float* base = lvl == 0 ? o0 : lvl == 1 ? o1 : lvl == 2 ? o2 : o3;
    int H = 256 >> lvl, HW = H * H;
    int NL = 3 * HW;
    int seg = b * 4 + lvl;
    float T = c_thr[lvl];
    const float4* p4 = (const float4*)(base + (long long)b * NL + c0);
    int n4 = n >> 2;
    for (int m = tid; m < n4; m += 512) {
        float4 v = p4[m];
        float vals[4] = {v.x, v.y, v.z, v.w};
#pragma unroll
        for (int s = 0; s < 4; s++) {
            if (vals[s] >= T) {
                unsigned u = fflip(vals[s]);
                int gm = c0 + m * 4 + s;
                int idx = (gm % HW) * 3 + gm / HW;   // (y*W+x)*A + a order
                int pos = atomicAdd(&g_ccnt[seg], 1);
                if (pos < CANDCAP)
                    g_cand[seg][pos] = (((unsigned long long)u) << 32) | (unsigned)(~idx);
            }
        }
    }
}

// -- stage 2: validate/sort -> top-512 -> decode + geometry; lvl0 merges ----
__global__ __launch_bounds__(512) void sortdecode_kernel(const float* __restrict__ o0,
                                                         const float* __restrict__ o1,
                                                         const float* __restrict__ o2,
                                                         const float* __restrict__ o3,
                                                         const float* __restrict__ d0,
                                                         const float* __restrict__ d1,
                                                         const float* __restrict__ d2,
                                                         const float* __restrict__ d3,
                                                         const float* __restrict__ anchors) {
    int seg = blockIdx.x;
    int sb = seg >> 2, slvl = seg & 3;
    __shared__ unsigned long long sk[CANDCAP];
    __shared__ int wtot[16], woff[16];
    __shared__ int s_tot;
    int tid = threadIdx.x;
    int sH = 256 >> slvl, sHW = sH * sH;
    int NL = 3 * sHW;

    int cnt = g_ccnt[seg];
    __syncthreads();
    if (tid == 0) g_ccnt[seg] = 0;

    if (cnt < PRE || cnt > CANDCAP) {
        // ---- exact fallback: full hist select for this segment ----
        const float* ob = slvl == 0 ? o0 : slvl == 1 ? o1 : slvl == 2 ? o2 : o3;
        const float* p = ob + (long long)sb * NL;
        int* h = (int*)sk;
        for (int i = tid; i < NBIN; i += 512) h[i] = 0;
        __syncthreads();
        for (int m = tid; m < NL; m += 512)
            atomicAdd(&h[fflip(p[m]) >> SHIFT], 1);
        __syncthreads();
        __shared__ unsigned s_fth;
        if (tid == 0) {
            int cum = 0, bin = NBIN - 1;
            for (; bin > 0; bin--) { cum += h[bin]; if (cum >= PRE) break; }
            s_fth = (unsigned)bin;
        }
        __syncthreads();
        unsigned fth = s_fth;
        for (int m = tid; m < NL; m += 512) {
            unsigned u = fflip(p[m]);
            if ((u >> SHIFT) >= fth) {
                int idx = (m % sHW) * 3 + m / sHW;
                int pp = atomicAdd(&g_ccnt[seg], 1);
                if (pp < CANDCAP)
                    g_cand[seg][pp] = (((unsigned long long)u) << 32) | (unsigned)(~idx);
            }
        }
        __threadfence();
        __syncthreads();
        cnt = g_ccnt[seg];
        if (cnt > CANDCAP) cnt = CANDCAP;
        __syncthreads();
        if (tid == 0) g_ccnt[seg] = 0;
        __syncthreads();
    }

    int M = (cnt <= 1024) ? 1024 : CANDCAP;
    for (int i = tid; i < M; i += 512)
        sk[i] = (i < cnt) ? g_cand[seg][i] : 0ull;
    __syncthreads();
    for (int ksz = 2; ksz <= M; ksz <<= 1) {
        for (int j = ksz >> 1; j > 0; j >>= 1) {
            for (int i = tid; i < M; i += 512) {
                int l = i ^ j;
                if (l > i) {
                    unsigned long long a = sk[i], c = sk[l];
                    bool desc = ((i & ksz) == 0);
                    if (desc ? (a < c) : (a > c)) { sk[i] = c; sk[l] = a; }
                }
            }
            __syncthreads();
        }
    }
    unsigned long long kk = sk[tid];
    float val = funflip((unsigned)(kk >> 32));
    int li = (int)(~(unsigned)(kk & 0xFFFFFFFFull));
    int a = li % 3, cell = li / 3;
    int x = cell % sH, y = cell / sH;
    const float* dl = slvl == 0 ? d0 : slvl == 1 ? d1 : slvl == 2 ? d2 : d3;
    long long bi = ((long long)sb * 18 + a * 6) * sHW + (long long)y * sH + x;
    float dx = dl[bi], dy = dl[bi + sHW], dw = dl[bi + 2LL * sHW],
          dh = dl[bi + 3LL * sHW], ds = dl[bi + 4LL * sHW], dc = dl[bi + 5LL * sHW];
    int ta = c_aoff[slvl] + li;
    const float* an = anchors + ((long long)sb * TANCH + ta) * 5;
    float ax = an[0], ay = an[1], aw = an[2], ah = an[3], aa = an[4];
    const float LOGM = 4.135166556742356f;
    dw = fminf(dw, LOGM);
    dh = fminf(dh, LOGM);
    float bw = aw * expf(dw), bh = ah * expf(dh);
    float bcx = ax + dx * aw, bcy = ay + dy * ah;
    float ang = aa + atan2f(ds, dc);
    float sc = 0.5f + 0.5f * tanhf(0.5f * val);       // XLA logistic form
    bool vd = (bw >= 1e-3f) && (bh >= 1e-3f) && (sc >= 0.0f);

    // stable compaction: valids to front, invalids to tail
    unsigned bal = __ballot_sync(0xffffffffu, vd);
    int lane = tid & 31, w = tid >> 5;
    int prew = __popc(bal & ((1u << lane) - 1u));
    if (lane == 0) wtot[w] = __popc(bal);
    __syncthreads();
    if (tid == 0) {
        int s = 0;
        for (int q = 0; q < 16; q++) { woff[q] = s; s += wtot[q]; }
        s_tot = s;
    }
    __syncthreads();
    int vbefore = woff[w] + prew;
    int rank = vd ? vbefore : (s_tot + (tid - vbefore));
    int pos = slvl * PRE + rank;

    g_box[sb][pos][0] = bcx; g_box[sb][pos][1] = bcy;
    g_box[sb][pos][2] = bw;  g_box[sb][pos][3] = bh;
    g_box[sb][pos][4] = ang;
    g_score[sb][pos] = sc;
    g_valid[sb][pos] = vd ? 1 : 0;
    unsigned u = vd ? __float_as_uint(sc) : 0u;       // score desc, pos asc tiebreak
    g_key[sb][pos] = (((unsigned long long)u) << 32) | (unsigned)(2047 - pos);

    {
        float off = 8192.0f * (float)slvl;
        float cx = bcx + off, cy = bcy + off;
        float ca = cosf(ang), sa = sinf(ang);
        float hw = 0.5f * bw, hh = 0.5f * bh;
        float dxs[4] = {hw, -hw, -hw, hw};
        float dys[4] = {hh, hh, -hh, -hh};
        float xmn = 1e30f, xmx = -1e30f, ymn = 1e30f, ymx = -1e30f;
        float* gp = &g_geom[sb][pos][0];
#pragma unroll
        for (int c = 0; c < 4; c++) {
            float xx = cx + dxs[c] * ca - dys[c] * sa;
            float yy = cy + dxs[c] * sa + dys[c] * ca;
            gp[2 * c] = xx;
            gp[2 * c + 1] = yy;
            xmn = fminf(xmn, xx); xmx = fmaxf(xmx, xx);
            ymn = fminf(ymn, yy); ymx = fmaxf(ymx, yy);
        }
        gp[8] = bw * bh;
        gp[9] = cx;
        gp[10] = cy;
        gp[11] = 0.5f * sqrtf(bw * bw + bh * bh);
        gp[12] = xmn;
        gp[13] = xmx;
        gp[14] = ymn;
        gp[15] = ymx;
    }

    // ---- publish this segment's run, then slvl==0 block merges the image --
    __threadfence();
    __syncthreads();
    if (tid == 0) atomicAdd(&g_imgarr[sb], 1);
    if (slvl != 0) return;
    if (tid == 0) {
        while (atomicAdd(&g_imgarr[sb], 0) < 4) {}
        g_imgarr[sb] = 0;
        __threadfence();
    }
    __syncthreads();
    if (tid < 32) g_rowany[sb][tid] = 0ull;
    for (int i = tid; i < NC; i += 512) sk[i] = __ldcg(&g_key[sb][i]);
    __syncthreads();

    // rank-scatter merge: 12 lockstep descending-count binary searches
    unsigned long long mkey[4];
#pragma unroll
    for (int L = 0; L < 4; L++) mkey[L] = sk[L * 512 + tid];
    int lo[4][3];
#pragma unroll
    for (int L = 0; L < 4; L++)
#pragma unroll
        for (int q = 0; q < 3; q++) lo[L][q] = 0;
#pragma unroll
    for (int step = 256; step > 0; step >>= 1) {
#pragma unroll
        for (int L = 0; L < 4; L++) {
#pragma unroll
            for (int q = 0; q < 3; q++) {
                int Mi = q + (q >= L ? 1 : 0);
                if (sk[Mi * 512 + lo[L][q] + step - 1] > mkey[L]) lo[L][q] += step;
            }
        }
    }
#pragma unroll
    for (int L = 0; L < 4; L++) {
        int mrank = tid;
#pragma unroll
        for (int q = 0; q < 3; q++) {
            int Mi = q + (q >= L ? 1 : 0);
            int c = lo[L][q];
            if (sk[Mi * 512 + c] > mkey[L]) c++;
            mrank += c;
        }
        int mpos = 2047 - (int)(unsigned)(mkey[L] & 0xFFFFFFFFull);
        unsigned mu = (unsigned)(mkey[L] >> 32);
        g_perm[sb][mrank] = mpos;
        g_svalid[sb][mrank] = mu != 0u ? 1 : 0;
        g_sscore[sb][mrank] = mu != 0u ? __uint_as_float(mu) : NINF;
    }
}

// ---------------- stage 3: rotated IoU suppression bitmask -----------------
__device__ float inter_area(float4 pA, float4 pB, float4 qA, float4 qB) {
    float px[8], py[8], ox[8], oy[8];
    px[0] = pA.x; py[0] = pA.y; px[1] = pA.z; py[1] = pA.w;
    px[2] = pB.x; py[2] = pB.y; px[3] = pB.z; py[3] = pB.w;
    float qx[4] = {qA.x, qA.z, qB.x, qB.z};
    float qy[4] = {qA.y, qA.w, qB.y, qB.w};
    int cnt = 4;
#pragma unroll
    for (int kk = 0; kk < 4; kk++) {
        float p1x = qx[kk], p1y = qy[kk];
        int k2 = (kk + 1) & 3;
        float ex = qx[k2] - p1x, ey = qy[k2] - p1y;
        int oc = 0;
        float d0 = ex * (py[0] - p1y) - ey * (px[0] - p1x);
        float dc = d0;
        for (int i = 0; i < cnt; i++) {
            int nx = (i + 1 < cnt) ? i + 1 : 0;
            float dn = (i + 1 < cnt) ? (ex * (py[i + 1] - p1y) - ey * (px[i + 1] - p1x)) : d0;
            bool ci = dc >= 0.f, ni = dn >= 0.f;
            if (ci) { ox[oc] = px[i]; oy[oc] = py[i]; oc++; }
            if (ci != ni) {
                float den = dc - dn;
                float tt = dc / ((den == 0.f) ? 1.f : den);
                ox[oc] = px[i] + tt * (px[nx] - px[i]);
                oy[oc] = py[i] + tt * (py[nx] - py[i]);
                oc++;
            }
            dc = dn;
        }
        cnt = oc;
        if (cnt == 0) break;
        for (int i = 0; i < cnt; i++) { px[i] = ox[i]; py[i] = oy[i]; }
    }
    if (cnt < 3) return 0.f;
    float s = 0.f;
    for (int i = 0; i < cnt; i++) {
        int nx = (i + 1 < cnt) ? i + 1 : 0;
        s += px[i] * py[nx] - px[nx] * py[i];
    }
    return 0.5f * fabsf(s);
}

// 512 threads = 8 tile-groups of 64; per-tile level-membership masks restrict
// the pair loop to same-level columns (cross-level IoU == 0 by construction:
// center distance >= 8192 > max radius sum, i.e. radius test always rejects).
__global__ __launch_bounds__(512) void mask_kernel() {
    int grp = threadIdx.x >> 6, lane = threadIdx.x & 63;
    int tile = blockIdx.x * 8 + grp;            // 2112 tiles, 264 blocks
    int img = tile / 528, tri = tile % 528;
    int rb = 0, rowrem = 32;
    while (tri >= rowrem) { tri -= rowrem; rowrem--; rb++; }
    int cb = rb + tri;

    __shared__ float4 sg[8][64][4];
    __shared__ int sperm[8][64];
    __shared__ unsigned mpart[8][2][4];
    __shared__ unsigned long long memb[8][4];
    const float4* gg = (const float4*)&g_geom[img][0][0];
    int colpos = g_perm[img][cb * 64 + lane];
    sperm[grp][lane] = colpos;
    int prow = g_perm[img][rb * 64 + lane];
    // membership ballots: which cols of this tile belong to each level
    {
        int collvl = colpos >> 9;                // pos -> level
        int half = lane >> 5;
#pragma unroll
        for (int l = 0; l < 4; l++) {
            unsigned bb = __ballot_sync(0xffffffffu, collvl == l);
            if ((lane & 31) == 0) mpart[grp][half][l] = bb;
        }
    }
    __syncthreads();
    for (int i = lane; i < 256; i += 64) {
        int box = i >> 2, k = i & 3;
        sg[grp][box][k] = gg[sperm[grp][box] * 4 + k];
    }
    if (lane < 4)
        memb[grp][lane] = (unsigned long long)mpart[grp][0][lane]
                        | ((unsigned long long)mpart[grp][1][lane] << 32);
    __syncthreads();

    int row = rb * 64 + lane;
    int mylvl = prow >> 9;
    float4 rA = gg[prow * 4 + 0];
    float4 rB = gg[prow * 4 + 1];
    float4 rC = gg[prow * 4 + 2];   // area, cx, cy, r
    float4 rD = gg[prow * 4 + 3];   // xmin, xmax, ymin, ymax

    unsigned long long surv = memb[grp][mylvl];
    if (cb == rb) surv &= (lane < 63) ? (~0ull << (lane + 1)) : 0ull;

    unsigned long long bits = 0;
    while (surv) {
        int j = __ffsll((long long)surv) - 1;
        surv &= surv - 1;
        float4 cC = sg[grp][j][2];
        float ddx = rC.y - cC.y, ddy = rC.z - cC.z;
        float rr = rC.w + cC.w;
        if (ddx * ddx + ddy * ddy >= rr * rr) continue;      // disjoint
        float mn = fminf(rC.x, cC.x), mx = fmaxf(rC.x, cC.x);
        if (mn <= 0.7f * mx) continue;                       // area-ratio bound
        float4 cD = sg[grp][j][3];
        float S = rC.x + cC.x;
        float xl = fmaxf(rD.x, cD.x), xr = fminf(rD.y, cD.y);
        float yl = fmaxf(rD.z, cD.z), yr = fminf(rD.w, cD.w);
        float ub = fmaxf(xr - xl, 0.f) * fmaxf(yr - yl, 0.f);
        if (ub * 1.7f < S * 0.6993f) continue;               // AABB bound (margin)
        float inter = inter_area(rA, rB, sg[grp][j][0], sg[grp][j][1]);
        float iou = inter / (S - inter + 1e-7f);
        if (iou > 0.7f) bits |= (1ull << j);
    }
    g_mask[img][row][cb] = bits;
    if (bits)
        atomicOr(&g_rowany[img][row >> 6], 1ull << (row & 63));
}

// ---------- stage 4: staged greedy (masks pre-staged in smem) --------------
__global__ __launch_bounds__(512) void greedy_out_kernel(float* __restrict__ out) {
    int b = blockIdx.x;
    int tid = threadIdx.x;
    __shared__ unsigned long long smask[SMAX][32];
    __shared__ int srcrow[SMAX];
    __shared__ unsigned long long s_ra[32];
    __shared__ unsigned long long s_remv[32];
    __shared__ int s_pfx[33];
    __shared__ int s_kpfx[33];
    __shared__ int s_S;

    if (tid < 32) s_ra[tid] = g_rowany[b][tid];
    __syncthreads();
    if (tid < 32) {
        int c = __popcll(s_ra[tid]);
        int p = c;
#pragma unroll
        for (int off = 1; off < 32; off <<= 1) {
            int v = __shfl_up_sync(0xffffffffu, p, off);
            if (tid >= off) p += v;
        }
        s_pfx[tid + 1] = p;
        if (tid == 0) s_pfx[0] = 0;
        if (tid == 31) s_S = (p < SMAX) ? p : SMAX;
    }
    __syncthreads();
    int S = s_S;
    for (int s = tid; s < S; s += 512) {
        int w = 0;
        while (s_pfx[w + 1] <= s) w++;
        srcrow[s] = w * 64 + sel64(s_ra[w], s - s_pfx[w]);
    }
    __syncthreads();
    for (int e = tid; e < S * 32; e += 512)
        smask[e >> 5][e & 31] = g_mask[b][srcrow[e >> 5]][e & 31];
    __syncthreads();

    if (tid < 32) {
        int lane = tid;
        unsigned long long remv = 0;
        const unsigned long long* vp = (const unsigned long long*)&g_svalid[b][lane * 64];
#pragma unroll
        for (int q = 0; q < 8; q++) {
            unsigned long long w8 = vp[q];
#pragma unroll
            for (int kk = 0; kk < 8; kk++)
                if (((w8 >> (kk * 8)) & 0xffull) == 0ull)
                    remv |= (1ull << (q * 8 + kk));
        }
        int sidx = 0, keeps = 0;
        for (int c = 0; c < 32; c++) {
            unsigned long long raw = s_ra[c];
            while (raw) {
                int k = __ffsll((long long)raw) - 1;
                raw &= raw - 1;
                unsigned long long wbits = __shfl_sync(0xffffffffu, remv, c);
                if (!((wbits >> k) & 1ull)) {
                    remv |= (sidx < S) ? smask[sidx][lane]
                                       : __ldcg(&g_mask[b][c * 64 + k][lane]);
                }
                sidx++;
            }
            unsigned long long wfin = __shfl_sync(0xffffffffu, remv, c);
            keeps += __popcll(~wfin);
            if (keeps >= PRE) break;
        }
        s_remv[lane] = remv;
    }
    __syncthreads();
    if (tid < 32) {
        int c = __popcll(~s_remv[tid]);
        int p = c;
#pragma unroll
        for (int off = 1; off < 32; off <<= 1) {
            int v = __shfl_up_sync(0xffffffffu, p, off);
            if (tid >= off) p += v;
        }
        s_kpfx[tid + 1] = p;
        if (tid == 0) s_kpfx[0] = 0;
    }
    __syncthreads();
    int total = s_kpfx[32];
    int n = total < PRE ? total : PRE;

    float v0 = 0, v1 = 0, v2 = 0, v3 = 0, v4 = 0, sc = 0;
    if (tid < n) {
        int w = 0;
        while (s_kpfx[w + 1] <= tid) w++;
        int i = w * 64 + sel64(~s_remv[w], tid - s_kpfx[w]);
        int pos = g_perm[b][i];
        v0 = g_box[b][pos][0]; v1 = g_box[b][pos][1];
        v2 = g_box[b][pos][2]; v3 = g_box[b][pos][3];
        v4 = g_box[b][pos][4];
        sc = g_sscore[b][i];
    }
    float* ob = out + ((long long)b * PRE + tid) * 5;
    ob[0] = v0; ob[1] = v1; ob[2] = v2; ob[3] = v3; ob[4] = v4;
    out[NB * PRE * 5 + b * PRE + tid] = sc;
}

extern "C" void kernel_launch(void* const* d_in, const int* in_sizes, int n_in,
                              void* d_out, int out_size) {
    const float* obj[4] = {0, 0, 0, 0};
    const float* dlt[4] = {0, 0, 0, 0};
    const float* anch = 0;
    const int osz[4] = {786432, 196608, 49152, 12288};
    const int dsz[4] = {4718592, 1179648, 294912, 73728};
    for (int i = 0; i < n_in; i++) {
        int s = in_sizes[i];
        const float* p = (const float*)d_in[i];
        if (s == 5222400) { anch = p; continue; }
        for (int l = 0; l < 4; l++) {
            if (s == osz[l]) obj[l] = p;
            else if (s == dsz[l]) dlt[l] = p;
        }
    }
    select_kernel<<<NBLK, 512>>>(obj[0], obj[1], obj[2], obj[3]);
    sortdecode_kernel<<<16, 512>>>(obj[0], obj[1], obj[2], obj[3],
                                   dlt[0], dlt[1], dlt[2], dlt[3], anch);
    mask_kernel<<<264, 512>>>();
    greedy_out_kernel<<<NB, 512>>>((float*)d_out);
}

// round 15
// speedup vs baseline: 1.0060x; 1.0060x over previous
#include <cuda_runtime.h>

#define NB 4
#define PRE 512
#define NC 2048
#define TANCH 261120
#define NBIN 4096
#define SHIFT 20
#define CANDCAP 2048
#define NBLK 264
#define SMAX 160
#define NINF __int_as_float(0xff800000)

// ---------------- scratch (device globals; zero-initialized) --------------
__device__ int g_ccnt[16];
__device__ int g_imgarr[NB];
__device__ unsigned long long g_rowany[NB][32];
__device__ unsigned long long g_cand[16][CANDCAP];
__device__ float g_box[NB][NC][5];                // pos-indexed
__device__ float g_score[NB][NC];                 // pos-indexed
__device__ unsigned char g_valid[NB][NC];         // pos-indexed
__device__ float g_geom[NB][NC][16];              // pos-indexed
__device__ unsigned long long g_key[NB][NC];
__device__ int g_perm[NB][NC];                    // sorted rank -> pos
__device__ unsigned char g_svalid[NB][NC];        // sorted order
__device__ float g_sscore[NB][NC];                // sorted order
__device__ unsigned long long g_mask[NB][NC][32];

__device__ const int c_aoff[4] = {0, 196608, 245760, 258048};
// static collect thresholds: ~top-900 quantile of N(0,1) per level size
// (exactness independent of these: out-of-range counts trigger exact fallback)
__device__ const float c_thr[4] = {2.605f, 2.090f, 1.4523f, 0.5446f};

__device__ __forceinline__ unsigned fflip(float f) {
    unsigned u = __float_as_uint(f);
    return (u & 0x80000000u) ? ~u : (u | 0x80000000u);
}
__device__ __forceinline__ float funflip(unsigned u) {
    return __uint_as_float((u & 0x80000000u) ? (u ^ 0x80000000u) : ~u);
}

__device__ __forceinline__ void map_block(int bx, int& b, int& lvl, int& c0, int& n) {
    b = bx / 66;
    int t = bx % 66;
    if (t < 48)      { lvl = 0; c0 = t * 4096;        n = 4096; }
    else if (t < 60) { lvl = 1; c0 = (t - 48) * 4096; n = 4096; }
    else if (t < 64) { lvl = 2; c0 = (t - 60) * 3072; n = 3072; }
    else             { lvl = 3; c0 = (t - 64) * 1536; n = 1536; }
}

// select the r-th (0-based) set bit of a 64-bit word
__device__ __forceinline__ int sel64(unsigned long long word, int r) {
    unsigned lo = (unsigned)word;
    int cl = __popc(lo);
    if (r < cl) return __fns(lo, 0, r + 1);
    return 32 + __fns((unsigned)(word >> 32), 0, r - cl + 1);
}

// ------------- stage 1: single-pass threshold collect ----------------------
__global__ __launch_bounds__(512) void select_kernel(const float* __restrict__ o0,
                                                     const float* __restrict__ o1,
                                                     const float* __restrict__ o2,
                                                     const float* __restrict__ o3) {
    int tid = threadIdx.x;
    int b, lvl, c0, n;
    map_block(blockIdx.x, b, lvl, c0, n);
    const float* base = lvl == 0 ? o0 : lvl == 1 ? o1 : lvl == 2 ? o2 : o3;
    int H = 256 >> lvl, HW = H * H;
    int NL = 3 * HW;
    int seg = b * 4 + lvl;
    float T = c_thr[lvl];
    const float4* p4 = (const float4*)(base + (long long)b * NL + c0);
    int n4 = n >> 2;
    for (int m = tid; m < n4; m += 512) {
        float4 v = p4[m];
        float vals[4] = {v.x, v.y, v.z, v.w};
#pragma unroll
        for (int s = 0; s < 4; s++) {
            if (vals[s] >= T) {
                unsigned u = fflip(vals[s]);
                int gm = c0 + m * 4 + s;
                int idx = (gm % HW) * 3 + gm / HW;   // (y*W+x)*A + a order
                int pos = atomicAdd(&g_ccnt[seg], 1);
                if (pos < CANDCAP)
                    g_cand[seg][pos] = (((unsigned long long)u) << 32) | (unsigned)(~idx);
            }
        }
    }
}

// -- stage 2: validate/sort -> top-512 -> decode + geometry; lvl0 merges ----
__global__ __launch_bounds__(512) void sortdecode_kernel(const float* __restrict__ o0,
                                                         const float* __restrict__ o1,
                                                         const float* __restrict__ o2,
                                                         const float* __restrict__ o3,
                                                         const float* __restrict__ d0,
                                                         const float* __restrict__ d1,
                                                         const float* __restrict__ d2,
                                                         const float* __restrict__ d3,
                                                         const float* __restrict__ anchors) {
    int seg = blockIdx.x;
    int sb = seg >> 2, slvl = seg & 3;
    __shared__ unsigned long long sk[CANDCAP];
    __shared__ int wtot[16], woff[16];
    __shared__ int s_tot;
    int tid = threadIdx.x;
    int sH = 256 >> slvl, sHW = sH * sH;
    int NL = 3 * sHW;

    int cnt = g_ccnt[seg];
    __syncthreads();
    if (tid == 0) g_ccnt[seg] = 0;

    if (cnt < PRE || cnt > CANDCAP) {
        // ---- exact fallback: full hist select for this segment ----
        const float* ob = slvl == 0 ? o0 : slvl == 1 ? o1 : slvl == 2 ? o2 : o3;
        const float* p = ob + (long long)sb * NL;
        int* h = (int*)sk;
        for (int i = tid; i < NBIN; i += 512) h[i] = 0;
        __syncthreads();
        for (int m = tid; m < NL; m += 512)
            atomicAdd(&h[fflip(p[m]) >> SHIFT], 1);
        __syncthreads();
        __shared__ unsigned s_fth;
        if (tid == 0) {
            int cum = 0, bin = NBIN - 1;
            for (; bin > 0; bin--) { cum += h[bin]; if (cum >= PRE) break; }
            s_fth = (unsigned)bin;
        }
        __syncthreads();
        unsigned fth = s_fth;
        for (int m = tid; m < NL; m += 512) {
            unsigned u = fflip(p[m]);
            if ((u >> SHIFT) >= fth) {
                int idx = (m % sHW) * 3 + m / sHW;
                int pp = atomicAdd(&g_ccnt[seg], 1);
                if (pp < CANDCAP)
                    g_cand[seg][pp] = (((unsigned long long)u) << 32) | (unsigned)(~idx);
            }
        }
        __threadfence();
        __syncthreads();
        cnt = g_ccnt[seg];
        if (cnt > CANDCAP) cnt = CANDCAP;
        __syncthreads();
        if (tid == 0) g_ccnt[seg] = 0;
        __syncthreads();
    }

    int M = (cnt <= 1024) ? 1024 : CANDCAP;
    for (int i = tid; i < M; i += 512)
        sk[i] = (i < cnt) ? g_cand[seg][i] : 0ull;
    __syncthreads();
    for (int ksz = 2; ksz <= M; ksz <<= 1) {
        for (int j = ksz >> 1; j > 0; j >>= 1) {
            for (int i = tid; i < M; i += 512) {
                int l = i ^ j;
                if (l > i) {
                    unsigned long long a = sk[i], c = sk[l];
                    bool desc = ((i & ksz) == 0);
                    if (desc ? (a < c) : (a > c)) { sk[i] = c; sk[l] = a; }
                }
            }
            __syncthreads();
        }
    }
    unsigned long long kk = sk[tid];
    float val = funflip((unsigned)(kk >> 32));
    int li = (int)(~(unsigned)(kk & 0xFFFFFFFFull));
    int a = li % 3, cell = li / 3;
    int x = cell % sH, y = cell / sH;
    const float* dl = slvl == 0 ? d0 : slvl == 1 ? d1 : slvl == 2 ? d2 : d3;
    long long bi = ((long long)sb * 18 + a * 6) * sHW + (long long)y * sH + x;
    float dx = dl[bi], dy = dl[bi + sHW], dw = dl[bi + 2LL * sHW],
          dh = dl[bi + 3LL * sHW], ds = dl[bi + 4LL * sHW], dc = dl[bi + 5LL * sHW];
    int ta = c_aoff[slvl] + li;
    const float* an = anchors + ((long long)sb * TANCH + ta) * 5;
    float ax = an[0], ay = an[1], aw = an[2], ah = an[3], aa = an[4];
    const float LOGM = 4.135166556742356f;
    dw = fminf(dw, LOGM);
    dh = fminf(dh, LOGM);
    float bw = aw * expf(dw), bh = ah * expf(dh);
    float bcx = ax + dx * aw, bcy = ay + dy * ah;
    float ang = aa + atan2f(ds, dc);
    float sc = 0.5f + 0.5f * tanhf(0.5f * val);       // XLA logistic form
    bool vd = (bw >= 1e-3f) && (bh >= 1e-3f) && (sc >= 0.0f);

    // stable compaction: valids to front, invalids to tail
    unsigned bal = __ballot_sync(0xffffffffu, vd);
    int lane = tid & 31, w = tid >> 5;
    int prew = __popc(bal & ((1u << lane) - 1u));
    if (lane == 0) wtot[w] = __popc(bal);
    __syncthreads();
    if (tid == 0) {
        int s = 0;
        for (int q = 0; q < 16; q++) { woff[q] = s; s += wtot[q]; }
        s_tot = s;
    }
    __syncthreads();
    int vbefore = woff[w] + prew;
    int rank = vd ? vbefore : (s_tot + (tid - vbefore));
    int pos = slvl * PRE + rank;

    g_box[sb][pos][0] = bcx; g_box[sb][pos][1] = bcy;
    g_box[sb][pos][2] = bw;  g_box[sb][pos][3] = bh;
    g_box[sb][pos][4] = ang;
    g_score[sb][pos] = sc;
    g_valid[sb][pos] = vd ? 1 : 0;
    unsigned u = vd ? __float_as_uint(sc) : 0u;       // score desc, pos asc tiebreak
    g_key[sb][pos] = (((unsigned long long)u) << 32) | (unsigned)(2047 - pos);

    {
        float off = 8192.0f * (float)slvl;
        float cx = bcx + off, cy = bcy + off;
        float ca = cosf(ang), sa = sinf(ang);
        float hw = 0.5f * bw, hh = 0.5f * bh;
        float dxs[4] = {hw, -hw, -hw, hw};
        float dys[4] = {hh, hh, -hh, -hh};
        float xmn = 1e30f, xmx = -1e30f, ymn = 1e30f, ymx = -1e30f;
        float* gp = &g_geom[sb][pos][0];
#pragma unroll
        for (int c = 0; c < 4; c++) {
            float xx = cx + dxs[c] * ca - dys[c] * sa;
            float yy = cy + dxs[c] * sa + dys[c] * ca;
            gp[2 * c] = xx;
            gp[2 * c + 1] = yy;
            xmn = fminf(xmn, xx); xmx = fmaxf(xmx, xx);
            ymn = fminf(ymn, yy); ymx = fmaxf(ymx, yy);
        }
        gp[8] = bw * bh;
        gp[9] = cx;
        gp[10] = cy;
        gp[11] = 0.5f * sqrtf(bw * bw + bh * bh);
        gp[12] = xmn;
        gp[13] = xmx;
        gp[14] = ymn;
        gp[15] = ymx;
    }

    // ---- publish this segment's run, then slvl==0 block merges the image --
    __threadfence();
    __syncthreads();
    if (tid == 0) atomicAdd(&g_imgarr[sb], 1);
    if (slvl != 0) return;
    if (tid == 0) {
        while (atomicAdd(&g_imgarr[sb], 0) < 4) {}
        g_imgarr[sb] = 0;
        __threadfence();
    }
    __syncthreads();
    if (tid < 32) g_rowany[sb][tid] = 0ull;
    for (int i = tid; i < NC; i += 512) sk[i] = __ldcg(&g_key[sb][i]);
    __syncthreads();

    // rank-scatter merge: 12 lockstep descending-count binary searches
    unsigned long long mkey[4];
#pragma unroll
    for (int L = 0; L < 4; L++) mkey[L] = sk[L * 512 + tid];
    int lo[4][3];
#pragma unroll
    for (int L = 0; L < 4; L++)
#pragma unroll
        for (int q = 0; q < 3; q++) lo[L][q] = 0;
#pragma unroll
    for (int step = 256; step > 0; step >>= 1) {
#pragma unroll
        for (int L = 0; L < 4; L++) {
#pragma unroll
            for (int q = 0; q < 3; q++) {
                int Mi = q + (q >= L ? 1 : 0);
                if (sk[Mi * 512 + lo[L][q] + step - 1] > mkey[L]) lo[L][q] += step;
            }
        }
    }
#pragma unroll
    for (int L = 0; L < 4; L++) {
        int mrank = tid;
#pragma unroll
        for (int q = 0; q < 3; q++) {
            int Mi = q + (q >= L ? 1 : 0);
            int c = lo[L][q];
            if (sk[Mi * 512 + c] > mkey[L]) c++;
            mrank += c;
        }
        int mpos = 2047 - (int)(unsigned)(mkey[L] & 0xFFFFFFFFull);
        unsigned mu = (unsigned)(mkey[L] >> 32);
        g_perm[sb][mrank] = mpos;
        g_svalid[sb][mrank] = mu != 0u ? 1 : 0;
        g_sscore[sb][mrank] = mu != 0u ? __uint_as_float(mu) : NINF;
    }
}

// ---------------- stage 3: rotated IoU suppression bitmask -----------------
__device__ float inter_area(float4 pA, float4 pB, float4 qA, float4 qB) {
    float px[8], py[8], ox[8], oy[8];
    px[0] = pA.x; py[0] = pA.y; px[1] = pA.z; py[1] = pA.w;
    px[2] = pB.x; py[2] = pB.y; px[3] = pB.z; py[3] = pB.w;
    float qx[4] = {qA.x, qA.z, qB.x, qB.z};
    float qy[4] = {qA.y, qA.w, qB.y, qB.w};
    int cnt = 4;
#pragma unroll
    for (int kk = 0; kk < 4; kk++) {
        float p1x = qx[kk], p1y = qy[kk];
        int k2 = (kk + 1) & 3;
        float ex = qx[k2] - p1x, ey = qy[k2] - p1y;
        int oc = 0;
        float d0 = ex * (py[0] - p1y) - ey * (px[0] - p1x);
        float dc = d0;
        for (int i = 0; i < cnt; i++) {
            int nx = (i + 1 < cnt) ? i + 1 : 0;
            float dn = (i + 1 < cnt) ? (ex * (py[i + 1] - p1y) - ey * (px[i + 1] - p1x)) : d0;
            bool ci = dc >= 0.f, ni = dn >= 0.f;
            if (ci) { ox[oc] = px[i]; oy[oc] = py[i]; oc++; }
            if (ci != ni) {
                float den = dc - dn;
                float tt = dc / ((den == 0.f) ? 1.f : den);
                ox[oc] = px[i] + tt * (px[nx] - px[i]);
                oy[oc] = py[i] + tt * (py[nx] - py[i]);
                oc++;
            }
            dc = dn;
        }
        cnt = oc;
        if (cnt == 0) break;
        for (int i = 0; i < cnt; i++) { px[i] = ox[i]; py[i] = oy[i]; }
    }
    if (cnt < 3) return 0.f;
    float s = 0.f;
    for (int i = 0; i < cnt; i++) {
        int nx = (i + 1 < cnt) ? i + 1 : 0;
        s += px[i] * py[nx] - px[nx] * py[i];
    }
    return 0.5f * fabsf(s);
}

// 512 threads = 8 tile-groups of 64; per-tile level-membership masks restrict
// the pair loop to same-level columns (cross-level IoU == 0 by construction:
// center distance >= 8192 > max radius sum, i.e. radius test always rejects).
__global__ __launch_bounds__(512) void mask_kernel() {
    int grp = threadIdx.x >> 6, lane = threadIdx.x & 63;
    int tile = blockIdx.x * 8 + grp;            // 2112 tiles, 264 blocks
    int img = tile / 528, tri = tile % 528;
    int rb = 0, rowrem = 32;
    while (tri >= rowrem) { tri -= rowrem; rowrem--; rb++; }
    int cb = rb + tri;

    __shared__ float4 sg[8][64][4];
    __shared__ int sperm[8][64];
    __shared__ unsigned mpart[8][2][4];
    __shared__ unsigned long long memb[8][4];
    const float4* gg = (const float4*)&g_geom[img][0][0];
    int colpos = g_perm[img][cb * 64 + lane];
    sperm[grp][lane] = colpos;
    int prow = g_perm[img][rb * 64 + lane];
    // membership ballots: which cols of this tile belong to each level
    {
        int collvl = colpos >> 9;                // pos -> level
        int half = lane >> 5;
#pragma unroll
        for (int l = 0; l < 4; l++) {
            unsigned bb = __ballot_sync(0xffffffffu, collvl == l);
            if ((lane & 31) == 0) mpart[grp][half][l] = bb;
        }
    }
    __syncthreads();
    for (int i = lane; i < 256; i += 64) {
        int box = i >> 2, k = i & 3;
        sg[grp][box][k] = gg[sperm[grp][box] * 4 + k];
    }
    if (lane < 4)
        memb[grp][lane] = (unsigned long long)mpart[grp][0][lane]
                        | ((unsigned long long)mpart[grp][1][lane] << 32);
    __syncthreads();

    int row = rb * 64 + lane;
    int mylvl = prow >> 9;
    float4 rA = gg[prow * 4 + 0];
    float4 rB = gg[prow * 4 + 1];
    float4 rC = gg[prow * 4 + 2];   // area, cx, cy, r
    float4 rD = gg[prow * 4 + 3];   // xmin, xmax, ymin, ymax

    unsigned long long surv = memb[grp][mylvl];
    if (cb == rb) surv &= (lane < 63) ? (~0ull << (lane + 1)) : 0ull;

    unsigned long long bits = 0;
    while (surv) {
        int j = __ffsll((long long)surv) - 1;
        surv &= surv - 1;
        float4 cC = sg[grp][j][2];
        float ddx = rC.y - cC.y, ddy = rC.z - cC.z;
        float rr = rC.w + cC.w;
        if (ddx * ddx + ddy * ddy >= rr * rr) continue;      // disjoint
        float mn = fminf(rC.x, cC.x), mx = fmaxf(rC.x, cC.x);
        if (mn <= 0.7f * mx) continue;                       // area-ratio bound
        float4 cD = sg[grp][j][3];
        float S = rC.x + cC.x;
        float xl = fmaxf(rD.x, cD.x), xr = fminf(rD.y, cD.y);
        float yl = fmaxf(rD.z, cD.z), yr = fminf(rD.w, cD.w);
        float ub = fmaxf(xr - xl, 0.f) * fmaxf(yr - yl, 0.f);
        if (ub * 1.7f < S * 0.6993f) continue;               // AABB bound (margin)
        float inter = inter_area(rA, rB, sg[grp][j][0], sg[grp][j][1]);
        float iou = inter / (S - inter + 1e-7f);
        if (iou > 0.7f) bits |= (1ull << j);
    }
    g_mask[img][row][cb] = bits;
    if (bits)
        atomicOr(&g_rowany[img][row >> 6], 1ull << (row & 63));
}

// ---------- stage 4: staged greedy (masks pre-staged in smem) --------------
__global__ __launch_bounds__(512) void greedy_out_kernel(float* __restrict__ out) {
    int b = blockIdx.x;
    int tid = threadIdx.x;
    __shared__ unsigned long long smask[SMAX][32];
    __shared__ int srcrow[SMAX];
    __shared__ unsigned long long s_ra[32];
    __shared__ unsigned long long s_remv[32];
    __shared__ int s_pfx[33];
    __shared__ int s_kpfx[33];
    __shared__ int s_S;

    if (tid < 32) s_ra[tid] = g_rowany[b][tid];
    __syncthreads();
    if (tid < 32) {
        int c = __popcll(s_ra[tid]);
        int p = c;
#pragma unroll
        for (int off = 1; off < 32; off <<= 1) {
            int v = __shfl_up_sync(0xffffffffu, p, off);
            if (tid >= off) p += v;
        }
        s_pfx[tid + 1] = p;
        if (tid == 0) s_pfx[0] = 0;
        if (tid == 31) s_S = (p < SMAX) ? p : SMAX;
    }
    __syncthreads();
    int S = s_S;
    for (int s = tid; s < S; s += 512) {
        int w = 0;
        while (s_pfx[w + 1] <= s) w++;
        srcrow[s] = w * 64 + sel64(s_ra[w], s - s_pfx[w]);
    }
    __syncthreads();
    for (int e = tid; e < S * 32; e += 512)
        smask[e >> 5][e & 31] = g_mask[b][srcrow[e >> 5]][e & 31];
    __syncthreads();

    if (tid < 32) {
        int lane = tid;
        unsigned long long remv = 0;
        const unsigned long long* vp = (const unsigned long long*)&g_svalid[b][lane * 64];
#pragma unroll
        for (int q = 0; q < 8; q++) {
            unsigned long long w8 = vp[q];
#pragma unroll
            for (int kk = 0; kk < 8; kk++)
                if (((w8 >> (kk * 8)) & 0xffull) == 0ull)
                    remv |= (1ull << (q * 8 + kk));
        }
        int sidx = 0, keeps = 0;
        for (int c = 0; c < 32; c++) {
            unsigned long long raw = s_ra[c];
            while (raw) {
                int k = __ffsll((long long)raw) - 1;
                raw &= raw - 1;
                unsigned long long wbits = __shfl_sync(0xffffffffu, remv, c);
                if (!((wbits >> k) & 1ull)) {
                    remv |= (sidx < S) ? smask[sidx][lane]
                                       : __ldcg(&g_mask[b][c * 64 + k][lane]);
                }
                sidx++;
            }
            unsigned long long wfin = __shfl_sync(0xffffffffu, remv, c);
            keeps += __popcll(~wfin);
            if (keeps >= PRE) break;
        }
        s_remv[lane] = remv;
    }
    __syncthreads();
    if (tid < 32) {
        int c = __popcll(~s_remv[tid]);
        int p = c;
#pragma unroll
        for (int off = 1; off < 32; off <<= 1) {
            int v = __shfl_up_sync(0xffffffffu, p, off);
            if (tid >= off) p += v;
        }
        s_kpfx[tid + 1] = p;
        if (tid == 0) s_kpfx[0] = 0;
    }
    __syncthreads();
    int total = s_kpfx[32];
    int n = total < PRE ? total : PRE;

    float v0 = 0, v1 = 0, v2 = 0, v3 = 0, v4 = 0, sc = 0;
    if (tid < n) {
        int w = 0;
        while (s_kpfx[w + 1] <= tid) w++;
        int i = w * 64 + sel64(~s_remv[w], tid - s_kpfx[w]);
        int pos = g_perm[b][i];
        v0 = g_box[b][pos][0]; v1 = g_box[b][pos][1];
        v2 = g_box[b][pos][2]; v3 = g_box[b][pos][3];
        v4 = g_box[b][pos][4];
        sc = g_sscore[b][i];
    }
    float* ob = out + ((long long)b * PRE + tid) * 5;
    ob[0] = v0; ob[1] = v1; ob[2] = v2; ob[3] = v3; ob[4] = v4;
    out[NB * PRE * 5 + b * PRE + tid] = sc;
}

extern "C" void kernel_launch(void* const* d_in, const int* in_sizes, int n_in,
                              void* d_out, int out_size) {
    const float* obj[4] = {0, 0, 0, 0};
    const float* dlt[4] = {0, 0, 0, 0};
    const float* anch = 0;
    const int osz[4] = {786432, 196608, 49152, 12288};
    const int dsz[4] = {4718592, 1179648, 294912, 73728};
    for (int i = 0; i < n_in; i++) {
        int s = in_sizes[i];
        const float* p = (const float*)d_in[i];
        if (s == 5222400) { anch = p; continue; }
        for (int l = 0; l < 4; l++) {
            if (s == osz[l]) obj[l] = p;
            else if (s == dsz[l]) dlt[l] = p;
        }
    }
    select_kernel<<<NBLK, 512>>>(obj[0], obj[1], obj[2], obj[3]);
    sortdecode_kernel<<<16, 512>>>(obj[0], obj[1], obj[2], obj[3],
                                   dlt[0], dlt[1], dlt[2], dlt[3], anch);
    mask_kernel<<<264, 512>>>();
    greedy_out_kernel<<<NB, 512>>>((float*)d_out);
}

// round 16
// speedup vs baseline: 1.3042x; 1.2965x over previous
#include <cuda_runtime.h>

#define NB 4
#define PRE 512
#define NC 2048
#define TANCH 261120
#define NBIN 4096
#define SHIFT 20
#define CANDCAP 2048
#define NBLK 264
#define SM2 96
#define NINF __int_as_float(0xff800000)

// ---------------- scratch (device globals; zero-initialized) --------------
__device__ int g_ccnt[16];
__device__ int g_imgarr[NB];
__device__ unsigned long long g_lrowany[NB][4][8];   // per-level row-any bits
__device__ unsigned long long g_cand[16][CANDCAP];
__device__ float g_box[NB][NC][5];                // pos-indexed
__device__ float g_score[NB][NC];                 // pos-indexed
__device__ unsigned char g_valid[NB][NC];         // pos-indexed
__device__ float g_geom[NB][NC][16];              // pos-indexed
__device__ unsigned long long g_key[NB][NC];
__device__ int g_perm[NB][NC];                    // sorted rank -> pos
__device__ float g_sscore[NB][NC];                // sorted order
__device__ unsigned long long g_lmask[NB][4][512][8];  // per-level masks

__device__ const int c_aoff[4] = {0, 196608, 245760, 258048};
// static collect thresholds (~top-900 N(0,1) quantile); exactness independent:
// out-of-range counts trigger the exact in-kernel fallback
__device__ const float c_thr[4] = {2.605f, 2.090f, 1.4523f, 0.5446f};

__device__ __forceinline__ unsigned fflip(float f) {
    unsigned u = __float_as_uint(f);
    return (u & 0x80000000u) ? ~u : (u | 0x80000000u);
}
__device__ __forceinline__ float funflip(unsigned u) {
    return __uint_as_float((u & 0x80000000u) ? (u ^ 0x80000000u) : ~u);
}

__device__ __forceinline__ void map_block(int bx, int& b, int& lvl, int& c0, int& n) {
    b = bx / 66;
    int t = bx % 66;
    if (t < 48)      { lvl = 0; c0 = t * 4096;        n = 4096; }
    else if (t < 60) { lvl = 1; c0 = (t - 48) * 4096; n = 4096; }
    else if (t < 64) { lvl = 2; c0 = (t - 60) * 3072; n = 3072; }
    else             { lvl = 3; c0 = (t - 64) * 1536; n = 1536; }
}

// select the r-th (0-based) set bit of a 64-bit word
__device__ __forceinline__ int sel64(unsigned long long word, int r) {
    unsigned lo = (unsigned)word;
    int cl = __popc(lo);
    if (r < cl) return __fns(lo, 0, r + 1);
    return 32 + __fns((unsigned)(word >> 32), 0, r - cl + 1);
}

// ------------- stage 1: single-pass threshold collect ----------------------
__global__ __launch_bounds__(512) void select_kernel(const float* __restrict__ o0,
                                                     const float* __restrict__ o1,
                                                     const float* __restrict__ o2,
                                                     const float* __restrict__ o3) {
    int tid = threadIdx.x;
    int b, lvl, c0, n;
    map_block(blockIdx.x, b, lvl, c0, n);
    const float* base = lvl == 0 ? o0 : lvl == 1 ? o1 : lvl == 2 ? o2 : o3;
    int H = 256 >> lvl, HW = H * H;
    int NL = 3 * HW;
    int seg = b * 4 + lvl;
    float T = c_thr[lvl];
    const float4* p4 = (const float4*)(base + (long long)b * NL + c0);
    int n4 = n >> 2;
    for (int m = tid; m < n4; m += 512) {
        float4 v = p4[m];
        float vals[4] = {v.x, v.y, v.z, v.w};
#pragma unroll
        for (int s = 0; s < 4; s++) {
            if (vals[s] >= T) {
                unsigned u = fflip(vals[s]);
                int gm = c0 + m * 4 + s;
                int idx = (gm % HW) * 3 + gm / HW;   // (y*W+x)*A + a order
                int pos = atomicAdd(&g_ccnt[seg], 1);
                if (pos < CANDCAP)
                    g_cand[seg][pos] = (((unsigned long long)u) << 32) | (unsigned)(~idx);
            }
        }
    }
}

// -- stage 2: validate/sort -> top-512 -> decode + geometry; lvl0 merges ----
__global__ __launch_bounds__(512) void sortdecode_kernel(const float* __restrict__ o0,
                                                         const float* __restrict__ o1,
                                                         const float* __restrict__ o2,
                                                         const float* __restrict__ o3,
                                                         const float* __restrict__ d0,
                                                         const float* __restrict__ d1,
                                                         const float* __restrict__ d2,
                                                         const float* __restrict__ d3,
                                                         const float* __restrict__ anchors) {
    int seg = blockIdx.x;
    int sb = seg >> 2, slvl = seg & 3;
    __shared__ unsigned long long sk[CANDCAP];
    __shared__ int wtot[16], woff[16];
    __shared__ int s_tot;
    int tid = threadIdx.x;
    int sH = 256 >> slvl, sHW = sH * sH;
    int NL = 3 * sHW;

    int cnt = g_ccnt[seg];
    __syncthreads();
    if (tid == 0) g_ccnt[seg] = 0;

    if (cnt < PRE || cnt > CANDCAP) {
        // ---- exact fallback: full hist select for this segment ----
        const float* ob = slvl == 0 ? o0 : slvl == 1 ? o1 : slvl == 2 ? o2 : o3;
        const float* p = ob + (long long)sb * NL;
        int* h = (int*)sk;
        for (int i = tid; i < NBIN; i += 512) h[i] = 0;
        __syncthreads();
        for (int m = tid; m < NL; m += 512)
            atomicAdd(&h[fflip(p[m]) >> SHIFT], 1);
        __syncthreads();
        __shared__ unsigned s_fth;
        if (tid == 0) {
            int cum = 0, bin = NBIN - 1;
            for (; bin > 0; bin--) { cum += h[bin]; if (cum >= PRE) break; }
            s_fth = (unsigned)bin;
        }
        __syncthreads();
        unsigned fth = s_fth;
        for (int m = tid; m < NL; m += 512) {
            unsigned u = fflip(p[m]);
            if ((u >> SHIFT) >= fth) {
                int idx = (m % sHW) * 3 + m / sHW;
                int pp = atomicAdd(&g_ccnt[seg], 1);
                if (pp < CANDCAP)
                    g_cand[seg][pp] = (((unsigned long long)u) << 32) | (unsigned)(~idx);
            }
        }
        __threadfence();
        __syncthreads();
        cnt = g_ccnt[seg];
        if (cnt > CANDCAP) cnt = CANDCAP;
        __syncthreads();
        if (tid == 0) g_ccnt[seg] = 0;
        __syncthreads();
    }

    int M = (cnt <= 1024) ? 1024 : CANDCAP;
    for (int i = tid; i < M; i += 512)
        sk[i] = (i < cnt) ? g_cand[seg][i] : 0ull;
    __syncthreads();
    for (int ksz = 2; ksz <= M; ksz <<= 1) {
        for (int j = ksz >> 1; j > 0; j >>= 1) {
            for (int i = tid; i < M; i += 512) {
                int l = i ^ j;
                if (l > i) {
                    unsigned long long a = sk[i], c = sk[l];
                    bool desc = ((i & ksz) == 0);
                    if (desc ? (a < c) : (a > c)) { sk[i] = c; sk[l] = a; }
                }
            }
            __syncthreads();
        }
    }
    unsigned long long kk = sk[tid];
    float val = funflip((unsigned)(kk >> 32));
    int li = (int)(~(unsigned)(kk & 0xFFFFFFFFull));
    int a = li % 3, cell = li / 3;
    int x = cell % sH, y = cell / sH;
    const float* dl = slvl == 0 ? d0 : slvl == 1 ? d1 : slvl == 2 ? d2 : d3;
    long long bi = ((long long)sb * 18 + a * 6) * sHW + (long long)y * sH + x;
    float dx = dl[bi], dy = dl[bi + sHW], dw = dl[bi + 2LL * sHW],
          dh = dl[bi + 3LL * sHW], ds = dl[bi + 4LL * sHW], dc = dl[bi + 5LL * sHW];
    int ta = c_aoff[slvl] + li;
    const float* an = anchors + ((long long)sb * TANCH + ta) * 5;
    float ax = an[0], ay = an[1], aw = an[2], ah = an[3], aa = an[4];
    const float LOGM = 4.135166556742356f;
    dw = fminf(dw, LOGM);
    dh = fminf(dh, LOGM);
    float bw = aw * expf(dw), bh = ah * expf(dh);
    float bcx = ax + dx * aw, bcy = ay + dy * ah;
    float ang = aa + atan2f(ds, dc);
    float sc = 0.5f + 0.5f * tanhf(0.5f * val);       // XLA logistic form
    bool vd = (bw >= 1e-3f) && (bh >= 1e-3f) && (sc >= 0.0f);

    // stable compaction: valids to front, invalids to tail
    unsigned bal = __ballot_sync(0xffffffffu, vd);
    int lane = tid & 31, w = tid >> 5;
    int prew = __popc(bal & ((1u << lane) - 1u));
    if (lane == 0) wtot[w] = __popc(bal);
    __syncthreads();
    if (tid == 0) {
        int s = 0;
        for (int q = 0; q < 16; q++) { woff[q] = s; s += wtot[q]; }
        s_tot = s;
    }
    __syncthreads();
    int vbefore = woff[w] + prew;
    int rank = vd ? vbefore : (s_tot + (tid - vbefore));
    int pos = slvl * PRE + rank;

    g_box[sb][pos][0] = bcx; g_box[sb][pos][1] = bcy;
    g_box[sb][pos][2] = bw;  g_box[sb][pos][3] = bh;
    g_box[sb][pos][4] = ang;
    g_score[sb][pos] = sc;
    g_valid[sb][pos] = vd ? 1 : 0;
    unsigned u = vd ? __float_as_uint(sc) : 0u;       // score desc, pos asc tiebreak
    g_key[sb][pos] = (((unsigned long long)u) << 32) | (unsigned)(2047 - pos);

    {
        float off = 8192.0f * (float)slvl;
        float cx = bcx + off, cy = bcy + off;
        float ca = cosf(ang), sa = sinf(ang);
        float hw = 0.5f * bw, hh = 0.5f * bh;
        float dxs[4] = {hw, -hw, -hw, hw};
        float dys[4] = {hh, hh, -hh, -hh};
        float xmn = 1e30f, xmx = -1e30f, ymn = 1e30f, ymx = -1e30f;
        float* gp = &g_geom[sb][pos][0];
#pragma unroll
        for (int c = 0; c < 4; c++) {
            float xx = cx + dxs[c] * ca - dys[c] * sa;
            float yy = cy + dxs[c] * sa + dys[c] * ca;
            gp[2 * c] = xx;
            gp[2 * c + 1] = yy;
            xmn = fminf(xmn, xx); xmx = fmaxf(xmx, xx);
            ymn = fminf(ymn, yy); ymx = fmaxf(ymx, yy);
        }
        gp[8] = bw * bh;
        gp[9] = cx;
        gp[10] = cy;
        gp[11] = 0.5f * sqrtf(bw * bw + bh * bh);
        gp[12] = xmn;
        gp[13] = xmx;
        gp[14] = ymn;
        gp[15] = ymx;
    }

    // ---- publish this segment's run, then slvl==0 block merges the image --
    __threadfence();
    __syncthreads();
    if (tid == 0) atomicAdd(&g_imgarr[sb], 1);
    if (slvl != 0) return;
    if (tid == 0) {
        while (atomicAdd(&g_imgarr[sb], 0) < 4) {}
        g_imgarr[sb] = 0;
        __threadfence();
    }
    __syncthreads();
    if (tid < 32) g_lrowany[sb][tid >> 3][tid & 7] = 0ull;   // reset for this replay
    for (int i = tid; i < NC; i += 512) sk[i] = __ldcg(&g_key[sb][i]);
    __syncthreads();

    // rank-scatter merge: 12 lockstep descending-count binary searches
    unsigned long long mkey[4];
#pragma unroll
    for (int L = 0; L < 4; L++) mkey[L] = sk[L * 512 + tid];
    int lo[4][3];
#pragma unroll
    for (int L = 0; L < 4; L++)
#pragma unroll
        for (int q = 0; q < 3; q++) lo[L][q] = 0;
#pragma unroll
    for (int step = 256; step > 0; step >>= 1) {
#pragma unroll
        for (int L = 0; L < 4; L++) {
#pragma unroll
            for (int q = 0; q < 3; q++) {
                int Mi = q + (q >= L ? 1 : 0);
                if (sk[Mi * 512 + lo[L][q] + step - 1] > mkey[L]) lo[L][q] += step;
            }
        }
    }
#pragma unroll
    for (int L = 0; L < 4; L++) {
        int mrank = tid;
#pragma unroll
        for (int q = 0; q < 3; q++) {
            int Mi = q + (q >= L ? 1 : 0);
            int c = lo[L][q];
            if (sk[Mi * 512 + c] > mkey[L]) c++;
            mrank += c;
        }
        int mpos = 2047 - (int)(unsigned)(mkey[L] & 0xFFFFFFFFull);
        unsigned mu = (unsigned)(mkey[L] >> 32);
        g_perm[sb][mrank] = mpos;
        g_sscore[sb][mrank] = mu != 0u ? __uint_as_float(mu) : NINF;
    }
}

// ------ stage 3: per-level rotated IoU masks (dense same-level tiles) ------
__device__ float inter_area(float4 pA, float4 pB, float4 qA, float4 qB) {
    float px[8], py[8], ox[8], oy[8];
    px[0] = pA.x; py[0] = pA.y; px[1] = pA.z; py[1] = pA.w;
    px[2] = pB.x; py[2] = pB.y; px[3] = pB.z; py[3] = pB.w;
    float qx[4] = {qA.x, qA.z, qB.x, qB.z};
    float qy[4] = {qA.y, qA.w, qB.y, qB.w};
    int cnt = 4;
#pragma unroll
    for (int kk = 0; kk < 4; kk++) {
        float p1x = qx[kk], p1y = qy[kk];
        int k2 = (kk + 1) & 3;
        float ex = qx[k2] - p1x, ey = qy[k2] - p1y;
        int oc = 0;
        float d0 = ex * (py[0] - p1y) - ey * (px[0] - p1x);
        float dc = d0;
        for (int i = 0; i < cnt; i++) {
            int nx = (i + 1 < cnt) ? i + 1 : 0;
            float dn = (i + 1 < cnt) ? (ex * (py[i + 1] - p1y) - ey * (px[i + 1] - p1x)) : d0;
            bool ci = dc >= 0.f, ni = dn >= 0.f;
            if (ci) { ox[oc] = px[i]; oy[oc] = py[i]; oc++; }
            if (ci != ni) {
                float den = dc - dn;
                float tt = dc / ((den == 0.f) ? 1.f : den);
                ox[oc] = px[i] + tt * (px[nx] - px[i]);
                oy[oc] = py[i] + tt * (py[nx] - py[i]);
                oc++;
            }
            dc = dn;
        }
        cnt = oc;
        if (cnt == 0) break;
        for (int i = 0; i < cnt; i++) { px[i] = ox[i]; py[i] = oy[i]; }
    }
    if (cnt < 3) return 0.f;
    float s = 0.f;
    for (int i = 0; i < cnt; i++) {
        int nx = (i + 1 < cnt) ? i + 1 : 0;
        s += px[i] * py[nx] - px[nx] * py[i];
    }
    return 0.5f * fabsf(s);
}

__global__ __launch_bounds__(256) void mask_kernel() {
    int grp = threadIdx.x >> 6, lane = threadIdx.x & 63;
    int tile = blockIdx.x * 4 + grp;        // 576 tiles = 4 img x 4 lvl x 36
    int img = tile / 144;
    int t2 = tile % 144;
    int lvl = t2 / 36;
    int tri = t2 % 36;
    int rb = 0, rowrem = 8;
    while (tri >= rowrem) { tri -= rowrem; rowrem--; rb++; }
    int cb = rb + tri;

    __shared__ float4 sg[4][64][4];
    const float4* gg = (const float4*)&g_geom[img][0][0];
    int colbase = lvl * 512 + cb * 64;
    for (int i = lane; i < 256; i += 64)
        ((float4*)sg[grp])[i] = gg[colbase * 4 + i];
    __syncthreads();

    int r = rb * 64 + lane;
    int pos = lvl * 512 + r;
    float4 rA = gg[pos * 4 + 0];
    float4 rB = gg[pos * 4 + 1];
    float4 rC = gg[pos * 4 + 2];   // area, cx, cy, radius
    float4 rD = gg[pos * 4 + 3];   // AABB

    // pass 1: branchless cheap filters
    unsigned long long surv = 0;
#pragma unroll 4
    for (int j = 0; j < 64; j++) {
        float4 cC = sg[grp][j][2];
        float ddx = rC.y - cC.y, ddy = rC.z - cC.z;
        float rr = rC.w + cC.w;
        float mn = fminf(rC.x, cC.x), mx = fmaxf(rC.x, cC.x);
        bool ok = (ddx * ddx + ddy * ddy < rr * rr) && (mn > 0.7f * mx);
        surv |= ((unsigned long long)ok) << j;
    }
    if (cb == rb) surv &= (lane < 63) ? (~0ull << (lane + 1)) : 0ull;

    // pass 2: exact checks on survivors
    unsigned long long bits = 0;
    while (surv) {
        int j = __ffsll((long long)surv) - 1;
        surv &= surv - 1;
        float4 cC = sg[grp][j][2];
        float4 cD = sg[grp][j][3];
        float S = rC.x + cC.x;
        float xl = fmaxf(rD.x, cD.x), xr = fminf(rD.y, cD.y);
        float yl = fmaxf(rD.z, cD.z), yr = fminf(rD.w, cD.w);
        float ub = fmaxf(xr - xl, 0.f) * fmaxf(yr - yl, 0.f);
        if (ub * 1.7f < S * 0.6993f) continue;
        float inter = inter_area(rA, rB, sg[grp][j][0], sg[grp][j][1]);
        float iou = inter / (S - inter + 1e-7f);
        if (iou > 0.7f) bits |= (1ull << j);
    }
    g_lmask[img][lvl][r][cb] = bits;
    if (bits)
        atomicOr(&g_lrowany[img][lvl][r >> 6], 1ull << (r & 63));
}

// --- stage 4: 4 parallel per-level greedies + parallel global selection ----
__global__ __launch_bounds__(512) void greedy_out_kernel(float* __restrict__ out) {
    int b = blockIdx.x;
    int tid = threadIdx.x;
    int wid = tid >> 5, lane = tid & 31;
    __shared__ unsigned long long smask[4][SM2][8];   // 24 KB staged masks
    __shared__ int srcrow[4][SM2];
    __shared__ unsigned long long s_ra[4][8];
    __shared__ unsigned long long s_kept[4][8];
    __shared__ int s_pfx[4][9];
    __shared__ unsigned kb32[64];
    __shared__ unsigned long long s_kw[32];
    __shared__ int s_kpfx[33];

    if (wid < 4) {
        int l = wid;
        unsigned long long ra = (lane < 8) ? g_lrowany[b][l][lane] : 0ull;
        if (lane < 8) s_ra[l][lane] = ra;
        // source-count prefix over 8 words
        int c = __popcll(ra);
        int p = c;
#pragma unroll
        for (int off = 1; off < 8; off <<= 1) {
            int v = __shfl_up_sync(0xffffffffu, p, off);
            if (lane >= off) p += v;
        }
        if (lane < 8) s_pfx[l][lane + 1] = p;
        if (lane == 0) s_pfx[l][0] = 0;
        __syncwarp();
        int S = s_pfx[l][8];
        if (S > SM2) S = SM2;
        for (int s = lane; s < S; s += 32) {
            int w = 0;
            while (s_pfx[l][w + 1] <= s) w++;
            srcrow[l][s] = w * 64 + sel64(s_ra[l][w], s - s_pfx[l][w]);
        }
        __syncwarp();
        for (int e = lane; e < S * 8; e += 32)
            smask[l][e >> 3][e & 7] = g_lmask[b][l][srcrow[l][e >> 3]][e & 7];
        __syncwarp();

        // remv init: invalid rows start suppressed
        unsigned long long remv = 0;
        if (lane < 8) {
            const unsigned long long* vp =
                (const unsigned long long*)&g_valid[b][l * 512 + lane * 64];
#pragma unroll
            for (int q = 0; q < 8; q++) {
                unsigned long long w8 = vp[q];
#pragma unroll
                for (int kk = 0; kk < 8; kk++)
                    if (((w8 >> (kk * 8)) & 0xffull) == 0ull)
                        remv |= (1ull << (q * 8 + kk));
            }
        }
        // chunked greedy over 8 chunks of 64 rows
        int sidx = 0;
        for (int c8 = 0; c8 < 8; c8++) {
            unsigned long long w = __shfl_sync(0xffffffffu, remv, c8);
            unsigned long long raw = __shfl_sync(0xffffffffu, ra, c8);
            while (raw) {
                int k = __ffsll((long long)raw) - 1;
                raw &= raw - 1;
                if (!((w >> k) & 1ull)) {              // source row is kept
                    if (lane < 8)
                        remv |= (sidx < S) ? smask[l][sidx][lane]
                                           : __ldcg(&g_lmask[b][l][c8 * 64 + k][lane]);
                    w = __shfl_sync(0xffffffffu, remv, c8);
                } 
                sidx++;
            }
        }
        if (lane < 8) s_kept[l][lane] = ~remv;
    }
    __syncthreads();

    // global kept flags in merged-score order -> 32 u64 words
#pragma unroll
    for (int t = 0; t < 4; t++) {
        int grank = t * 512 + tid;
        int pos = g_perm[b][grank];
        int l = pos >> 9, r = pos & 511;
        bool kept = (s_kept[l][r >> 6] >> (r & 63)) & 1ull;
        unsigned bb = __ballot_sync(0xffffffffu, kept);
        if (lane == 0) kb32[t * 16 + wid] = bb;
    }
    __syncthreads();
    if (tid < 32)
        s_kw[tid] = (unsigned long long)kb32[2 * tid]
                  | ((unsigned long long)kb32[2 * tid + 1] << 32);
    __syncthreads();
    if (tid < 32) {
        int c = __popcll(s_kw[tid]);
        int p = c;
#pragma unroll
        for (int off = 1; off < 32; off <<= 1) {
            int v = __shfl_up_sync(0xffffffffu, p, off);
            if (tid >= off) p += v;
        }
        s_kpfx[tid + 1] = p;
        if (tid == 0) s_kpfx[0] = 0;
    }
    __syncthreads();
    int total = s_kpfx[32];
    int n = total < PRE ? total : PRE;

    float v0 = 0, v1 = 0, v2 = 0, v3 = 0, v4 = 0, sc = 0;
    if (tid < n) {
        int w = 0;
        while (s_kpfx[w + 1] <= tid) w++;
        int i = w * 64 + sel64(s_kw[w], tid - s_kpfx[w]);
        int pos = g_perm[b][i];
        v0 = g_box[b][pos][0]; v1 = g_box[b][pos][1];
        v2 = g_box[b][pos][2]; v3 = g_box[b][pos][3];
        v4 = g_box[b][pos][4];
        sc = g_sscore[b][i];
    }
    float* ob = out + ((long long)b * PRE + tid) * 5;
    ob[0] = v0; ob[1] = v1; ob[2] = v2; ob[3] = v3; ob[4] = v4;
    out[NB * PRE * 5 + b * PRE + tid] = sc;
}

extern "C" void kernel_launch(void* const* d_in, const int* in_sizes, int n_in,
                              void* d_out, int out_size) {
    const float* obj[4] = {0, 0, 0, 0};
    const float* dlt[4] = {0, 0, 0, 0};
    const float* anch = 0;
    const int osz[4] = {786432, 196608, 49152, 12288};
    const int dsz[4] = {4718592, 1179648, 294912, 73728};
    for (int i = 0; i < n_in; i++) {
        int s = in_sizes[i];
        const float* p = (const float*)d_in[i];
        if (s == 5222400) { anch = p; continue; }
        for (int l = 0; l < 4; l++) {
            if (s == osz[l]) obj[l] = p;
            else if (s == dsz[l]) dlt[l] = p;
        }
    }
    select_kernel<<<NBLK, 512>>>(obj[0], obj[1], obj[2], obj[3]);
    sortdecode_kernel<<<16, 512>>>(obj[0], obj[1], obj[2], obj[3],
                                   dlt[0], dlt[1], dlt[2], dlt[3], anch);
    mask_kernel<<<144, 256>>>();
    greedy_out_kernel<<<NB, 512>>>((float*)d_out);
}